// round 1
// baseline (speedup 1.0000x reference)
#include <cuda_runtime.h>
#include <math.h>

#define BATCH   4
#define SEQ     2048
#define DMODEL  1024
#define DFF     4096
#define NHEADS  16
#define DK      64
#define MROWS   (BATCH*SEQ)      // 8192
#define BHCNT   (BATCH*NHEADS)   // 64

// ---- scratch (static device globals: the sanctioned no-alloc workaround) ----
__device__ float g_ln1[(size_t)MROWS*DMODEL];
__device__ float g_q  [(size_t)MROWS*DMODEL];
__device__ float g_k  [(size_t)MROWS*DMODEL];
__device__ float g_v  [(size_t)MROWS*DMODEL];
__device__ float g_att[(size_t)MROWS*DMODEL];
__device__ float g_x1 [(size_t)MROWS*DMODEL];
__device__ float g_ln2[(size_t)MROWS*DMODEL];
__device__ float g_ff [(size_t)MROWS*DFF];
__device__ float g_sc [(size_t)BHCNT*SEQ*SEQ];   // 1 GiB scores scratch

// ============================ LayerNorm ============================
__global__ void ln_kernel(const float* __restrict__ in, const float* __restrict__ gam,
                          const float* __restrict__ bet, float* __restrict__ out)
{
    int row = blockIdx.x;
    const float4* xp = reinterpret_cast<const float4*>(in + (size_t)row * DMODEL);
    float4 v = xp[threadIdx.x];            // 256 threads * 4 = 1024 elems
    float s  = v.x + v.y + v.z + v.w;
    float ss = v.x*v.x + v.y*v.y + v.z*v.z + v.w*v.w;
    __shared__ float red[16];
    #pragma unroll
    for (int o = 16; o; o >>= 1) {
        s  += __shfl_xor_sync(0xffffffffu, s,  o);
        ss += __shfl_xor_sync(0xffffffffu, ss, o);
    }
    int w = threadIdx.x >> 5, l = threadIdx.x & 31;
    if (l == 0) { red[w] = s; red[w + 8] = ss; }
    __syncthreads();
    if (threadIdx.x < 32) {
        s  = red[l & 7];
        ss = red[(l & 7) + 8];
        #pragma unroll
        for (int o = 4; o; o >>= 1) {
            s  += __shfl_xor_sync(0xffffffffu, s,  o);
            ss += __shfl_xor_sync(0xffffffffu, ss, o);
        }
        if (l == 0) { red[0] = s; red[1] = ss; }
    }
    __syncthreads();
    float mean = red[0] * (1.0f / DMODEL);
    float var  = red[1] * (1.0f / DMODEL) - mean * mean;
    float rstd = rsqrtf(var + 1e-5f);
    float4 gg = reinterpret_cast<const float4*>(gam)[threadIdx.x];
    float4 bb = reinterpret_cast<const float4*>(bet)[threadIdx.x];
    float4 o;
    o.x = (v.x - mean) * rstd * gg.x + bb.x;
    o.y = (v.y - mean) * rstd * gg.y + bb.y;
    o.z = (v.z - mean) * rstd * gg.z + bb.z;
    o.w = (v.w - mean) * rstd * gg.w + bb.w;
    reinterpret_cast<float4*>(out + (size_t)row * DMODEL)[threadIdx.x] = o;
}

// ============================ SGEMM 128x128x8 ============================
// C[M,N] = A[M,K] @ W[K,N] + bias, epilogue: 0=bias, 1=bias+GELU(exact), 2=bias+residual
template<int EPI>
__global__ void __launch_bounds__(256) sgemm_kernel(
    const float* __restrict__ A, const float* __restrict__ W,
    const float* __restrict__ bias, const float* __restrict__ R,
    float* __restrict__ C, int K, int N)
{
    __shared__ float As[8][128];
    __shared__ float Bs[8][128];
    const int tid = threadIdx.x;
    const int m0 = blockIdx.y * 128, n0 = blockIdx.x * 128;
    const int a_row = tid >> 1, a_k = (tid & 1) * 4;     // 128 rows x 8 k
    const int b_k = tid >> 5, b_n = (tid & 31) * 4;      // 8 k x 128 n
    const float* Ap = A + (size_t)(m0 + a_row) * K + a_k;
    const float* Wp = W + (size_t)b_k * N + n0 + b_n;
    const int ty = tid >> 4, tx = tid & 15;
    float acc[8][8];
    #pragma unroll
    for (int i = 0; i < 8; i++)
        #pragma unroll
        for (int j = 0; j < 8; j++) acc[i][j] = 0.f;

    for (int k0 = 0; k0 < K; k0 += 8) {
        float4 av = *reinterpret_cast<const float4*>(Ap + k0);
        float4 wv = *reinterpret_cast<const float4*>(Wp + (size_t)k0 * N);
        __syncthreads();
        As[a_k + 0][a_row] = av.x;
        As[a_k + 1][a_row] = av.y;
        As[a_k + 2][a_row] = av.z;
        As[a_k + 3][a_row] = av.w;
        *reinterpret_cast<float4*>(&Bs[b_k][b_n]) = wv;
        __syncthreads();
        #pragma unroll
        for (int kk = 0; kk < 8; kk++) {
            float a[8], b[8];
            *reinterpret_cast<float4*>(a)     = *reinterpret_cast<const float4*>(&As[kk][ty * 8]);
            *reinterpret_cast<float4*>(a + 4) = *reinterpret_cast<const float4*>(&As[kk][ty * 8 + 4]);
            *reinterpret_cast<float4*>(b)     = *reinterpret_cast<const float4*>(&Bs[kk][tx * 8]);
            *reinterpret_cast<float4*>(b + 4) = *reinterpret_cast<const float4*>(&Bs[kk][tx * 8 + 4]);
            #pragma unroll
            for (int i = 0; i < 8; i++)
                #pragma unroll
                for (int j = 0; j < 8; j++)
                    acc[i][j] = fmaf(a[i], b[j], acc[i][j]);
        }
    }
    float bvv[8];
    #pragma unroll
    for (int j = 0; j < 8; j++) bvv[j] = bias[n0 + tx * 8 + j];
    #pragma unroll
    for (int i = 0; i < 8; i++) {
        const int m = m0 + ty * 8 + i;
        float* cp = C + (size_t)m * N + n0 + tx * 8;
        float o[8];
        #pragma unroll
        for (int j = 0; j < 8; j++) {
            float vv = acc[i][j] + bvv[j];
            if (EPI == 1) vv = 0.5f * vv * (1.0f + erff(vv * 0.70710678118654752f));
            if (EPI == 2) vv += R[(size_t)m * N + n0 + tx * 8 + j];
            o[j] = vv;
        }
        *reinterpret_cast<float4*>(cp)     = *reinterpret_cast<const float4*>(o);
        *reinterpret_cast<float4*>(cp + 4) = *reinterpret_cast<const float4*>(o + 4);
    }
}

// ============================ scores = Q K^T * scale (causal tile skip) ============================
// 128x128 tile of scores per block, K-dim = 64 (head dim). Entries with j>i are
// written unmasked but never consumed (softmax reads only j<=i).
__global__ void __launch_bounds__(256) scores_kernel(
    const float* __restrict__ Q, const float* __restrict__ Kmat, float* __restrict__ SC)
{
    const int jt = blockIdx.x, it = blockIdx.y;
    if (jt > it) return;
    const int bh = blockIdx.z;
    const int b = bh >> 4, h = bh & 15;
    __shared__ float Qs[8][128];
    __shared__ float Ks[8][128];
    const int tid = threadIdx.x;
    const int a_row = tid >> 1, a_k = (tid & 1) * 4;
    const float* Qp = Q    + (size_t)(b * SEQ + it * 128 + a_row) * DMODEL + h * DK + a_k;
    const float* Kp = Kmat + (size_t)(b * SEQ + jt * 128 + a_row) * DMODEL + h * DK + a_k;
    const int ty = tid >> 4, tx = tid & 15;
    float acc[8][8];
    #pragma unroll
    for (int i = 0; i < 8; i++)
        #pragma unroll
        for (int j = 0; j < 8; j++) acc[i][j] = 0.f;

    for (int d0 = 0; d0 < DK; d0 += 8) {
        float4 qv = *reinterpret_cast<const float4*>(Qp + d0);
        float4 kv = *reinterpret_cast<const float4*>(Kp + d0);
        __syncthreads();
        Qs[a_k + 0][a_row] = qv.x; Qs[a_k + 1][a_row] = qv.y;
        Qs[a_k + 2][a_row] = qv.z; Qs[a_k + 3][a_row] = qv.w;
        Ks[a_k + 0][a_row] = kv.x; Ks[a_k + 1][a_row] = kv.y;
        Ks[a_k + 2][a_row] = kv.z; Ks[a_k + 3][a_row] = kv.w;
        __syncthreads();
        #pragma unroll
        for (int kk = 0; kk < 8; kk++) {
            float a[8], b[8];
            *reinterpret_cast<float4*>(a)     = *reinterpret_cast<const float4*>(&Qs[kk][ty * 8]);
            *reinterpret_cast<float4*>(a + 4) = *reinterpret_cast<const float4*>(&Qs[kk][ty * 8 + 4]);
            *reinterpret_cast<float4*>(b)     = *reinterpret_cast<const float4*>(&Ks[kk][tx * 8]);
            *reinterpret_cast<float4*>(b + 4) = *reinterpret_cast<const float4*>(&Ks[kk][tx * 8 + 4]);
            #pragma unroll
            for (int i = 0; i < 8; i++)
                #pragma unroll
                for (int j = 0; j < 8; j++)
                    acc[i][j] = fmaf(a[i], b[j], acc[i][j]);
        }
    }
    #pragma unroll
    for (int i = 0; i < 8; i++) {
        const int row = it * 128 + ty * 8 + i;
        float* sp = SC + ((size_t)bh * SEQ + row) * SEQ + jt * 128 + tx * 8;
        float o[8];
        #pragma unroll
        for (int j = 0; j < 8; j++) o[j] = acc[i][j] * 0.125f;   // 1/sqrt(64)
        *reinterpret_cast<float4*>(sp)     = *reinterpret_cast<const float4*>(o);
        *reinterpret_cast<float4*>(sp + 4) = *reinterpret_cast<const float4*>(o + 4);
    }
}

// ============================ causal row softmax + zero pad to 128 ============================
__global__ void softmax_kernel(float* __restrict__ SC)
{
    const int i = blockIdx.x, bh = blockIdx.y;
    float* row = SC + ((size_t)bh * SEQ + i) * SEQ;
    const int L = i + 1;
    const int tid = threadIdx.x;
    __shared__ float sm[8];

    float mx = -3.0e38f;
    for (int j = tid; j < L; j += 256) mx = fmaxf(mx, row[j]);
    #pragma unroll
    for (int o = 16; o; o >>= 1) mx = fmaxf(mx, __shfl_xor_sync(0xffffffffu, mx, o));
    if ((tid & 31) == 0) sm[tid >> 5] = mx;
    __syncthreads();
    mx = sm[0];
    #pragma unroll
    for (int w = 1; w < 8; w++) mx = fmaxf(mx, sm[w]);
    __syncthreads();

    float s = 0.f;
    for (int j = tid; j < L; j += 256) {
        float e = __expf(row[j] - mx);
        row[j] = e;
        s += e;
    }
    #pragma unroll
    for (int o = 16; o; o >>= 1) s += __shfl_xor_sync(0xffffffffu, s, o);
    if ((tid & 31) == 0) sm[tid >> 5] = s;
    __syncthreads();
    s = 0.f;
    #pragma unroll
    for (int w = 0; w < 8; w++) s += sm[w];
    const float inv = 1.0f / s;
    for (int j = tid; j < L; j += 256) row[j] *= inv;
    // zero-pad row up to the next 128 boundary so the PV GEMM needs no mask
    const int pad = ((L + 127) >> 7) << 7;
    for (int j = L + tid; j < pad; j += 256) row[j] = 0.f;
}

// ============================ out = P @ V (causal K-length) ============================
// 128 (rows) x 64 (head dim) output tile per block; j runs to it*128+128 (zeros beyond diag).
__global__ void __launch_bounds__(256) av_kernel(
    const float* __restrict__ P, const float* __restrict__ V, float* __restrict__ O)
{
    const int it = blockIdx.x, bh = blockIdx.y;
    const int b = bh >> 4, h = bh & 15;
    __shared__ float Ps[8][128];
    __shared__ float Vs[8][64];
    const int tid = threadIdx.x;
    const int a_row = tid >> 1, a_k = (tid & 1) * 4;
    const float* Pp = P + ((size_t)bh * SEQ + it * 128 + a_row) * SEQ + a_k;
    const int b_k = tid >> 5, b_n = (tid & 31) * 2;
    const float* Vp = V + (size_t)(b * SEQ + b_k) * DMODEL + h * DK + b_n;
    const int Klen = it * 128 + 128;
    const int ty = tid >> 4, tx = tid & 15;
    float acc[8][4];
    #pragma unroll
    for (int i = 0; i < 8; i++)
        #pragma unroll
        for (int j = 0; j < 4; j++) acc[i][j] = 0.f;

    for (int k0 = 0; k0 < Klen; k0 += 8) {
        float4 pv = *reinterpret_cast<const float4*>(Pp + k0);
        float2 vv = *reinterpret_cast<const float2*>(Vp + (size_t)k0 * DMODEL);
        __syncthreads();
        Ps[a_k + 0][a_row] = pv.x; Ps[a_k + 1][a_row] = pv.y;
        Ps[a_k + 2][a_row] = pv.z; Ps[a_k + 3][a_row] = pv.w;
        *reinterpret_cast<float2*>(&Vs[b_k][b_n]) = vv;
        __syncthreads();
        #pragma unroll
        for (int kk = 0; kk < 8; kk++) {
            float a[8], bb[4];
            *reinterpret_cast<float4*>(a)     = *reinterpret_cast<const float4*>(&Ps[kk][ty * 8]);
            *reinterpret_cast<float4*>(a + 4) = *reinterpret_cast<const float4*>(&Ps[kk][ty * 8 + 4]);
            *reinterpret_cast<float4*>(bb)    = *reinterpret_cast<const float4*>(&Vs[kk][tx * 4]);
            #pragma unroll
            for (int i = 0; i < 8; i++)
                #pragma unroll
                for (int j = 0; j < 4; j++)
                    acc[i][j] = fmaf(a[i], bb[j], acc[i][j]);
        }
    }
    #pragma unroll
    for (int i = 0; i < 8; i++) {
        const int srow = it * 128 + ty * 8 + i;
        float* op = O + (size_t)(b * SEQ + srow) * DMODEL + h * DK + tx * 4;
        float4 o = make_float4(acc[i][0], acc[i][1], acc[i][2], acc[i][3]);
        *reinterpret_cast<float4*>(op) = o;
    }
}

// ============================ orchestration ============================
extern "C" void kernel_launch(void* const* d_in, const int* in_sizes, int n_in,
                              void* d_out, int out_size)
{
    (void)in_sizes; (void)n_in; (void)out_size;
    const float* x    = (const float*)d_in[0];
    const float* Wq   = (const float*)d_in[1];
    const float* bq   = (const float*)d_in[2];
    const float* Wk   = (const float*)d_in[3];
    const float* bk   = (const float*)d_in[4];
    const float* Wv   = (const float*)d_in[5];
    const float* bv   = (const float*)d_in[6];
    const float* Wo   = (const float*)d_in[7];
    const float* bo   = (const float*)d_in[8];
    const float* ln1g = (const float*)d_in[9];
    const float* ln1b = (const float*)d_in[10];
    const float* ln2g = (const float*)d_in[11];
    const float* ln2b = (const float*)d_in[12];
    const float* W1   = (const float*)d_in[13];
    const float* b1   = (const float*)d_in[14];
    const float* W2   = (const float*)d_in[15];
    const float* b2   = (const float*)d_in[16];
    float* out = (float*)d_out;

    float *p_ln1, *p_q, *p_k, *p_v, *p_att, *p_x1, *p_ln2, *p_ff, *p_sc;
    cudaGetSymbolAddress((void**)&p_ln1, g_ln1);
    cudaGetSymbolAddress((void**)&p_q,   g_q);
    cudaGetSymbolAddress((void**)&p_k,   g_k);
    cudaGetSymbolAddress((void**)&p_v,   g_v);
    cudaGetSymbolAddress((void**)&p_att, g_att);
    cudaGetSymbolAddress((void**)&p_x1,  g_x1);
    cudaGetSymbolAddress((void**)&p_ln2, g_ln2);
    cudaGetSymbolAddress((void**)&p_ff,  g_ff);
    cudaGetSymbolAddress((void**)&p_sc,  g_sc);

    const dim3 gDD(DMODEL / 128, MROWS / 128);   // (8, 64)

    // x -> LN1
    ln_kernel<<<MROWS, 256>>>(x, ln1g, ln1b, p_ln1);
    // Q, K, V projections (+bias)
    sgemm_kernel<0><<<gDD, 256>>>(p_ln1, Wq, bq, nullptr, p_q, DMODEL, DMODEL);
    sgemm_kernel<0><<<gDD, 256>>>(p_ln1, Wk, bk, nullptr, p_k, DMODEL, DMODEL);
    sgemm_kernel<0><<<gDD, 256>>>(p_ln1, Wv, bv, nullptr, p_v, DMODEL, DMODEL);
    // scores = QK^T * scale (causal tiles only)
    scores_kernel<<<dim3(SEQ / 128, SEQ / 128, BHCNT), 256>>>(p_q, p_k, p_sc);
    // causal softmax + zero pad
    softmax_kernel<<<dim3(SEQ, BHCNT), 256>>>(p_sc);
    // attn = P @ V
    av_kernel<<<dim3(SEQ / 128, BHCNT), 256>>>(p_sc, p_v, p_att);
    // O-projection + bias + residual(x) -> x1
    sgemm_kernel<2><<<gDD, 256>>>(p_att, Wo, bo, x, p_x1, DMODEL, DMODEL);
    // LN2
    ln_kernel<<<MROWS, 256>>>(p_x1, ln2g, ln2b, p_ln2);
    // FFN1 + bias + exact GELU
    sgemm_kernel<1><<<dim3(DFF / 128, MROWS / 128), 256>>>(p_ln2, W1, b1, nullptr, p_ff, DMODEL, DFF);
    // FFN2 + bias + residual(x1) -> out
    sgemm_kernel<2><<<gDD, 256>>>(p_ff, W2, b2, p_x1, out, DFF, DMODEL);
}